// round 6
// baseline (speedup 1.0000x reference)
#include <cuda_runtime.h>
#include <cstdint>

// ---------------------------------------------------------------------------
// PolicyHead fused kernel v2: one block per image, 512 threads.
//   y[361x64] = x[361x256] @ [w_p*ivp | w_g*ivg]   (mma.sync tf32, fp32 accum)
//   g: relu(y_g + cg) -> mean/max pool -> bias, pass logits
//   p: relu(y_p + cp) @ w_out -> pi_main / pi_aux
// cp.async 4-stage pipeline for x; warps split N (8 M-warps x 2 N-halves).
// ---------------------------------------------------------------------------

#define NIMG    2048
#define HW      361
#define OUTW    362
#define AUXOFF  (NIMG * OUTW)
#define EPSF    1e-3f

// shared memory word offsets
#define ABUF     7680          // one A stage: 384 rows * 20 words
#define OFF_A    0             // 4 stages = 30720 words
#define OFF_B    30720         // 256 rows * 72 words = 18432
#define OFF_WB   49152         // 64*32
#define OFF_WO   51200         // 64
#define OFF_CG   51264         // 32
#define OFF_CP   51296         // 32
#define OFF_POOL 51328         // 64
#define OFF_RS   51392         // 8*32
#define OFF_RM   51648         // 8*32
#define SMEM_WORDS 51904
#define SMEM_BYTES (SMEM_WORDS * 4)   // 207,616 B

__device__ __forceinline__ uint32_t f2tf32(float f) {
    uint32_t u;
    asm("cvt.rna.tf32.f32 %0, %1;" : "=r"(u) : "f"(f));
    return u;
}

__device__ __forceinline__ void mma_tf32(float c[4],
                                         uint32_t a0, uint32_t a1,
                                         uint32_t a2, uint32_t a3,
                                         uint32_t b0, uint32_t b1) {
    asm volatile(
        "mma.sync.aligned.m16n8k8.row.col.f32.tf32.tf32.f32 "
        "{%0,%1,%2,%3}, {%4,%5,%6,%7}, {%8,%9}, {%0,%1,%2,%3};"
        : "+f"(c[0]), "+f"(c[1]), "+f"(c[2]), "+f"(c[3])
        : "r"(a0), "r"(a1), "r"(a2), "r"(a3), "r"(b0), "r"(b1));
}

__device__ __forceinline__ void cpa16(uint32_t dst, const void* src, int pred) {
    asm volatile(
        "{\n\t"
        ".reg .pred p;\n\t"
        "setp.ne.b32 p, %0, 0;\n\t"
        "@p cp.async.cg.shared.global [%1], [%2], 16;\n\t"
        "}"
        :: "r"(pred), "r"(dst), "l"(src) : "memory");
}

__global__ void __launch_bounds__(512, 1) policy_head_kernel(
    const float* __restrict__ x,
    const float* __restrict__ w_p,  const float* __restrict__ w_g,
    const float* __restrict__ beta_g, const float* __restrict__ mean_g,
    const float* __restrict__ var_g,
    const float* __restrict__ w_bias, const float* __restrict__ b_bias,
    const float* __restrict__ beta_p, const float* __restrict__ mean_p,
    const float* __restrict__ var_p,
    const float* __restrict__ w_out,
    const float* __restrict__ w_pass, const float* __restrict__ b_pass,
    float* __restrict__ out)
{
    extern __shared__ uint32_t sm[];
    float* smf = reinterpret_cast<float*>(sm);

    const int tid  = threadIdx.x;
    const int lane = tid & 31;
    const int w    = tid >> 5;          // warp 0..15
    const int q    = lane & 3;
    const int g    = lane >> 2;
    const int wm   = w >> 1;            // M-warp 0..7
    const int wq   = w & 1;             // N-half: 0=p, 1=g
    const int img  = blockIdx.x;
    const int imgBase = img * HW;
    const float4* x4 = reinterpret_cast<const float4*>(x);
    const uint32_t smb = (uint32_t)__cvta_generic_to_shared(sm);

    // ---------------- issue cp.async for chunks 0..2 ------------------------
#pragma unroll
    for (int c = 0; c < 3; ++c) {
#pragma unroll
        for (int it = 0; it < 3; ++it) {
            int idx = tid + it * 512;
            int r = idx >> 2, c4 = idx & 3;
            uint32_t dst = smb + (uint32_t)((c * ABUF + r * 20 + c4 * 4) * 4);
            const float4* src = x4 + (imgBase + r) * 64 + c * 4 + c4;
            cpa16(dst, src, r < HW);
        }
        asm volatile("cp.async.commit_group;" ::: "memory");
    }

    // zero-pad rows 361..383 in all 4 stage buffers (written once, never dirtied)
    for (int i = tid; i < 4 * 23 * 20; i += 512) {
        int b = i / (23 * 20), rem = i % (23 * 20);
        sm[b * ABUF + (361 + rem / 20) * 20 + rem % 20] = 0;
    }

    // ---------------- build B (folded BN scale), cache small weights --------
    for (int i = tid; i < 256 * 64; i += 512) {
        int k = i >> 6, n = i & 63;
        float v;
        if (n < 32) v = w_p[k * 32 + n] * rsqrtf(var_p[n] + EPSF);
        else { int d = n - 32; v = w_g[k * 32 + d] * rsqrtf(var_g[d] + EPSF); }
        sm[OFF_B + k * 72 + n] = f2tf32(v);
    }
    for (int i = tid; i < 2048; i += 512) smf[OFF_WB + i] = w_bias[i];
    if (tid < 32) {
        smf[OFF_WO + tid]      = w_out[tid * 2];
        smf[OFF_WO + 32 + tid] = w_out[tid * 2 + 1];
        smf[OFF_CG + tid] = beta_g[tid] - mean_g[tid] * rsqrtf(var_g[tid] + EPSF);
    }

    float acc[3][4][4];
#pragma unroll
    for (int m = 0; m < 3; ++m)
#pragma unroll
        for (int n = 0; n < 4; ++n)
#pragma unroll
            for (int j = 0; j < 4; ++j) acc[m][n][j] = 0.f;

    __syncthreads();   // B / pads / small weights visible

    // ---------------- main loop: 16 K-chunks of 16, 4-stage pipeline --------
    for (int c = 0; c < 16; ++c) {
        asm volatile("cp.async.wait_group 2;" ::: "memory");  // chunk c resident
        __syncthreads();                                      // visible to all; stage (c-1)&3 free

        if (c + 3 < 16) {
            const int cc = c + 3;
#pragma unroll
            for (int it = 0; it < 3; ++it) {
                int idx = tid + it * 512;
                int r = idx >> 2, c4 = idx & 3;
                uint32_t dst = smb + (uint32_t)(((cc & 3) * ABUF + r * 20 + c4 * 4) * 4);
                const float4* src = x4 + (imgBase + r) * 64 + cc * 4 + c4;
                cpa16(dst, src, r < HW);
            }
            asm volatile("cp.async.commit_group;" ::: "memory");
        }

        const uint32_t* Ab = sm + (c & 3) * ABUF;
        const uint32_t* Bb = sm + OFF_B + (c * 16) * 72;
#pragma unroll
        for (int s = 0; s < 2; ++s) {
            uint32_t bf[4][2];
#pragma unroll
            for (int nt = 0; nt < 4; ++nt) {
                int NT = wq * 4 + nt;
                bf[nt][0] = Bb[(s * 8 + q) * 72 + NT * 8 + g];
                bf[nt][1] = Bb[(s * 8 + q + 4) * 72 + NT * 8 + g];
            }
#pragma unroll
            for (int m = 0; m < 3; ++m) {
                int mt = wm + m * 8;
                const uint32_t* ap = Ab + (mt * 16 + g) * 20 + s * 8 + q;
                uint32_t a0 = f2tf32(__uint_as_float(ap[0]));
                uint32_t a2 = f2tf32(__uint_as_float(ap[4]));
                uint32_t a1 = f2tf32(__uint_as_float(ap[8 * 20]));
                uint32_t a3 = f2tf32(__uint_as_float(ap[8 * 20 + 4]));
#pragma unroll
                for (int nt = 0; nt < 4; ++nt)
                    mma_tf32(acc[m][nt], a0, a1, a2, a3, bf[nt][0], bf[nt][1]);
            }
        }
    }

    // ---------------- g-branch pooling (wq==1 warps own g channels) ---------
    if (wq == 1) {
#pragma unroll
        for (int nt = 0; nt < 4; ++nt) {
#pragma unroll
            for (int j = 0; j < 2; ++j) {
                int ch = nt * 8 + 2 * q + j;
                float cg = smf[OFF_CG + ch];
                float s = 0.f, mx = 0.f;
#pragma unroll
                for (int m = 0; m < 3; ++m) {
                    int r0 = (wm + m * 8) * 16 + g;
                    float v0 = fmaxf(acc[m][nt][j] + cg, 0.f);
                    float v1 = fmaxf(acc[m][nt][2 + j] + cg, 0.f);
                    if (r0 >= HW) v0 = 0.f;
                    if (r0 + 8 >= HW) v1 = 0.f;
                    s += v0 + v1;
                    mx = fmaxf(mx, fmaxf(v0, v1));
                }
#pragma unroll
                for (int o = 4; o <= 16; o <<= 1) {
                    s += __shfl_xor_sync(0xffffffffu, s, o);
                    mx = fmaxf(mx, __shfl_xor_sync(0xffffffffu, mx, o));
                }
                if (g == 0) {
                    smf[OFF_RS + wm * 32 + ch] = s;
                    smf[OFF_RM + wm * 32 + ch] = mx;
                }
            }
        }
    }
    __syncthreads();

    // ---------------- warp 0: pooled bias, cp offset, pass logits -----------
    if (w == 0) {
        float s = 0.f, mx = 0.f;
#pragma unroll
        for (int wi = 0; wi < 8; ++wi) {
            s += smf[OFF_RS + wi * 32 + lane];
            mx = fmaxf(mx, smf[OFF_RM + wi * 32 + lane]);
        }
        smf[OFF_POOL + lane]      = s * (1.f / 361.f);
        smf[OFF_POOL + 32 + lane] = mx;
        __syncwarp();

        float bias = b_bias[lane];
#pragma unroll
        for (int j = 0; j < 64; ++j)
            bias += smf[OFF_POOL + j] * smf[OFF_WB + j * 32 + lane];
        float ivp = rsqrtf(var_p[lane] + EPSF);
        smf[OFF_CP + lane] = (bias - mean_p[lane]) * ivp + beta_p[lane];

        if (lane < 2) {
            float pv = b_pass[lane] - 3.0f;
#pragma unroll
            for (int j = 0; j < 64; ++j)
                pv += smf[OFF_POOL + j] * w_pass[j * 2 + lane];
            out[(lane ? AUXOFF : 0) + img * OUTW + HW] = pv;
        }
    }
    __syncthreads();

    // ---------------- p-branch epilogue (wq==0 warps own p channels) --------
    if (wq == 0) {
#pragma unroll
        for (int m = 0; m < 3; ++m) {
            int mt = wm + m * 8;
#pragma unroll
            for (int h = 0; h < 2; ++h) {
                int r = mt * 16 + g + 8 * h;
                float p0 = 0.f, p1 = 0.f;
#pragma unroll
                for (int nt = 0; nt < 4; ++nt) {
#pragma unroll
                    for (int j = 0; j < 2; ++j) {
                        int ch = nt * 8 + 2 * q + j;
                        float vv = fmaxf(acc[m][nt][2 * h + j] + smf[OFF_CP + ch], 0.f);
                        p0 += vv * smf[OFF_WO + ch];
                        p1 += vv * smf[OFF_WO + 32 + ch];
                    }
                }
                p0 += __shfl_xor_sync(0xffffffffu, p0, 1);
                p0 += __shfl_xor_sync(0xffffffffu, p0, 2);
                p1 += __shfl_xor_sync(0xffffffffu, p1, 1);
                p1 += __shfl_xor_sync(0xffffffffu, p1, 2);
                if (q == 0 && r < HW) {
                    out[img * OUTW + r]          = p0;
                    out[AUXOFF + img * OUTW + r] = p1;
                }
            }
        }
    }
}

extern "C" void kernel_launch(void* const* d_in, const int* in_sizes, int n_in,
                              void* d_out, int out_size) {
    (void)in_sizes; (void)n_in; (void)out_size;
    cudaFuncSetAttribute(policy_head_kernel,
                         cudaFuncAttributeMaxDynamicSharedMemorySize, SMEM_BYTES);
    policy_head_kernel<<<NIMG, 512, SMEM_BYTES>>>(
        (const float*)d_in[0],  (const float*)d_in[1],  (const float*)d_in[2],
        (const float*)d_in[3],  (const float*)d_in[4],  (const float*)d_in[5],
        (const float*)d_in[6],  (const float*)d_in[7],  (const float*)d_in[8],
        (const float*)d_in[9],  (const float*)d_in[10], (const float*)d_in[11],
        (const float*)d_in[12], (const float*)d_in[13],
        (float*)d_out);
}

// round 7
// speedup vs baseline: 1.3475x; 1.3475x over previous
#include <cuda_runtime.h>
#include <cstdint>

// ---------------------------------------------------------------------------
// PolicyHead fused kernel v3: one block per image, 512 threads, 16 warps.
//   y[361x64] = x[361x256] @ [w_p*ivp | w_g*ivg]   (mma.sync tf32, fp32 accum)
//   g: relu(y_g + cg) -> mean/max pool -> bias, pass logits
//   p: relu(y_p + cp) @ w_out -> pi_main / pi_aux
// B matrix pre-folded to tf32 by an init kernel; per-block cp.async of B.
// A: LDG->cvt(rna)->STS double buffer, K-chunk 32, 8 barriers total.
// Warps: wm = M-warp (0..7), wq = N-half (0: p-channels, 1: g-channels).
// ---------------------------------------------------------------------------

#define NIMG    2048
#define HW      361
#define OUTW    362
#define AUXOFF  (NIMG * OUTW)
#define EPSF    1e-3f

// shared memory word offsets
#define OFF_A0   0            // 384 rows * 36 words = 13824
#define OFF_A1   13824
#define OFF_B    27648        // 256 rows * 72 words = 18432
#define OFF_WB   46080        // 2048
#define OFF_WO   48128        // 64
#define OFF_CG   48192        // 32
#define OFF_CP   48224        // 32
#define OFF_POOL 48256        // 64
#define OFF_RS   48320        // 8*32
#define OFF_RM   48576        // 8*32
#define SMEM_WORDS 48832
#define SMEM_BYTES (SMEM_WORDS * 4)   // 195,328 B

__device__ uint32_t g_Btf[256 * 64];   // BN-folded weight matrix, tf32 bits

__device__ __forceinline__ uint32_t f2tf32(float f) {
    uint32_t u;
    asm("cvt.rna.tf32.f32 %0, %1;" : "=r"(u) : "f"(f));
    return u;
}

__device__ __forceinline__ void mma_tf32(float c[4],
                                         uint32_t a0, uint32_t a1,
                                         uint32_t a2, uint32_t a3,
                                         uint32_t b0, uint32_t b1) {
    asm volatile(
        "mma.sync.aligned.m16n8k8.row.col.f32.tf32.tf32.f32 "
        "{%0,%1,%2,%3}, {%4,%5,%6,%7}, {%8,%9}, {%0,%1,%2,%3};"
        : "+f"(c[0]), "+f"(c[1]), "+f"(c[2]), "+f"(c[3])
        : "r"(a0), "r"(a1), "r"(a2), "r"(a3), "r"(b0), "r"(b1));
}

__device__ __forceinline__ void cpa16(uint32_t dst, const void* src) {
    asm volatile("cp.async.cg.shared.global [%0], [%1], 16;"
                 :: "r"(dst), "l"(src) : "memory");
}

// ---- init: fold BN inverse-std into the 256x64 weight tile (tf32) ----------
__global__ void policy_init(const float* __restrict__ w_p,
                            const float* __restrict__ w_g,
                            const float* __restrict__ var_p,
                            const float* __restrict__ var_g) {
    int i = blockIdx.x * 256 + threadIdx.x;   // 0..16383
    int k = i >> 6, n = i & 63;
    float v = (n < 32)
        ? w_p[k * 32 + n] * rsqrtf(var_p[n] + EPSF)
        : w_g[k * 32 + (n - 32)] * rsqrtf(var_g[n - 32] + EPSF);
    g_Btf[i] = f2tf32(v);
}

__global__ void __launch_bounds__(512, 1) policy_head_kernel(
    const float* __restrict__ x,
    const float* __restrict__ beta_g, const float* __restrict__ mean_g,
    const float* __restrict__ var_g,
    const float* __restrict__ w_bias, const float* __restrict__ b_bias,
    const float* __restrict__ beta_p, const float* __restrict__ mean_p,
    const float* __restrict__ var_p,
    const float* __restrict__ w_out,
    const float* __restrict__ w_pass, const float* __restrict__ b_pass,
    float* __restrict__ out)
{
    extern __shared__ uint32_t sm[];
    float* smf = reinterpret_cast<float*>(sm);

    const int tid  = threadIdx.x;
    const int lane = tid & 31;
    const int w    = tid >> 5;          // warp 0..15
    const int q    = lane & 3;
    const int g    = lane >> 2;
    const int wm   = w >> 1;            // M-warp 0..7
    const int wq   = w & 1;             // N-half: 0=p, 1=g
    const int img  = blockIdx.x;
    const int imgBase = img * HW;
    const float4* x4 = reinterpret_cast<const float4*>(x);
    const uint32_t smb = (uint32_t)__cvta_generic_to_shared(sm);

    // ---- prologue: cp.async B (padded stride 72) + w_bias; small weights ---
#pragma unroll
    for (int it = 0; it < 8; ++it) {
        int idx = tid + it * 512;               // 0..4095
        int row = idx >> 4, seg = idx & 15;
        cpa16(smb + (uint32_t)((OFF_B + row * 72 + seg * 4) * 4),
              g_Btf + row * 64 + seg * 4);
    }
    cpa16(smb + (uint32_t)((OFF_WB + tid * 4) * 4), w_bias + tid * 4);
    asm volatile("cp.async.commit_group;" ::: "memory");

    if (tid < 32) {
        smf[OFF_WO + tid]      = w_out[tid * 2];
        smf[OFF_WO + 32 + tid] = w_out[tid * 2 + 1];
        smf[OFF_CG + tid] = beta_g[tid] - mean_g[tid] * rsqrtf(var_g[tid] + EPSF);
    }

    float acc[3][4][4];
#pragma unroll
    for (int m = 0; m < 3; ++m)
#pragma unroll
        for (int n = 0; n < 4; ++n)
#pragma unroll
            for (int j = 0; j < 4; ++j) acc[m][n][j] = 0.f;

    // ---- chunk 0: LDG -> cvt -> STS into A0 --------------------------------
    float4 v[6];
#pragma unroll
    for (int it = 0; it < 6; ++it) {
        int idx = tid + it * 512;               // 0..3071
        int r = idx >> 3, c4 = idx & 7;
        v[it] = make_float4(0.f, 0.f, 0.f, 0.f);
        if (r < HW) v[it] = x4[(imgBase + r) * 64 + c4];
    }
#pragma unroll
    for (int it = 0; it < 6; ++it) {
        int idx = tid + it * 512;
        int r = idx >> 3, c4 = idx & 7;
        uint32_t* d = sm + OFF_A0 + r * 36 + c4 * 4;
        d[0] = f2tf32(v[it].x); d[1] = f2tf32(v[it].y);
        d[2] = f2tf32(v[it].z); d[3] = f2tf32(v[it].w);
    }
    asm volatile("cp.async.wait_group 0;" ::: "memory");
    __syncthreads();

    // ---- main loop: 8 K-chunks of 32, double-buffered A --------------------
    for (int c = 0; c < 8; ++c) {
        // prefetch chunk c+1 into registers (per-warp latency hiding)
        if (c < 7) {
#pragma unroll
            for (int it = 0; it < 6; ++it) {
                int idx = tid + it * 512;
                int r = idx >> 3, c4 = idx & 7;
                v[it] = make_float4(0.f, 0.f, 0.f, 0.f);
                if (r < HW) v[it] = x4[(imgBase + r) * 64 + (c + 1) * 8 + c4];
            }
        }

        const uint32_t* Ab = sm + ((c & 1) ? OFF_A1 : OFF_A0);
        const uint32_t* Bb = sm + OFF_B + (c * 32) * 72;
#pragma unroll
        for (int s = 0; s < 4; ++s) {
            uint32_t bf[4][2];
#pragma unroll
            for (int nt = 0; nt < 4; ++nt) {
                int NT = wq * 4 + nt;
                bf[nt][0] = Bb[(s * 8 + q) * 72 + NT * 8 + g];
                bf[nt][1] = Bb[(s * 8 + q + 4) * 72 + NT * 8 + g];
            }
#pragma unroll
            for (int m = 0; m < 3; ++m) {
                int mt = wm + m * 8;
                const uint32_t* ap = Ab + (mt * 16 + g) * 36 + s * 8 + q;
                uint32_t a0 = ap[0], a2 = ap[4];
                uint32_t a1 = ap[8 * 36], a3 = ap[8 * 36 + 4];
#pragma unroll
                for (int nt = 0; nt < 4; ++nt)
                    mma_tf32(acc[m][nt], a0, a1, a2, a3, bf[nt][0], bf[nt][1]);
            }
        }

        if (c < 7) {
            uint32_t* d0 = sm + ((c & 1) ? OFF_A0 : OFF_A1);
#pragma unroll
            for (int it = 0; it < 6; ++it) {
                int idx = tid + it * 512;
                int r = idx >> 3, c4 = idx & 7;
                uint32_t* d = d0 + r * 36 + c4 * 4;
                d[0] = f2tf32(v[it].x); d[1] = f2tf32(v[it].y);
                d[2] = f2tf32(v[it].z); d[3] = f2tf32(v[it].w);
            }
        }
        __syncthreads();
    }

    // ---- g-branch pooling (wq==1 warps own g channels) ----------------------
    if (wq == 1) {
#pragma unroll
        for (int nt = 0; nt < 4; ++nt) {
#pragma unroll
            for (int j = 0; j < 2; ++j) {
                int ch = nt * 8 + 2 * q + j;
                float cg = smf[OFF_CG + ch];
                float s = 0.f, mx = 0.f;
#pragma unroll
                for (int m = 0; m < 3; ++m) {
                    int r0 = (wm + m * 8) * 16 + g;
                    float v0 = fmaxf(acc[m][nt][j] + cg, 0.f);
                    float v1 = fmaxf(acc[m][nt][2 + j] + cg, 0.f);
                    if (r0 >= HW) v0 = 0.f;
                    if (r0 + 8 >= HW) v1 = 0.f;
                    s += v0 + v1;
                    mx = fmaxf(mx, fmaxf(v0, v1));
                }
#pragma unroll
                for (int o = 4; o <= 16; o <<= 1) {
                    s += __shfl_xor_sync(0xffffffffu, s, o);
                    mx = fmaxf(mx, __shfl_xor_sync(0xffffffffu, mx, o));
                }
                if (g == 0) {
                    smf[OFF_RS + wm * 32 + ch] = s;
                    smf[OFF_RM + wm * 32 + ch] = mx;
                }
            }
        }
    }
    __syncthreads();

    // ---- warp 0: pooled bias, cp offset, pass logits ------------------------
    if (w == 0) {
        float s = 0.f, mx = 0.f;
#pragma unroll
        for (int wi = 0; wi < 8; ++wi) {
            s += smf[OFF_RS + wi * 32 + lane];
            mx = fmaxf(mx, smf[OFF_RM + wi * 32 + lane]);
        }
        smf[OFF_POOL + lane]      = s * (1.f / 361.f);
        smf[OFF_POOL + 32 + lane] = mx;
        __syncwarp();

        float bias = b_bias[lane];
#pragma unroll
        for (int j = 0; j < 64; ++j)
            bias += smf[OFF_POOL + j] * smf[OFF_WB + j * 32 + lane];
        float ivp = rsqrtf(var_p[lane] + EPSF);
        smf[OFF_CP + lane] = (bias - mean_p[lane]) * ivp + beta_p[lane];

        if (lane < 2) {
            float pv = b_pass[lane] - 3.0f;
#pragma unroll
            for (int j = 0; j < 64; ++j)
                pv += smf[OFF_POOL + j] * w_pass[j * 2 + lane];
            out[(lane ? AUXOFF : 0) + img * OUTW + HW] = pv;
        }
    }
    __syncthreads();

    // ---- p-branch epilogue (wq==0 warps own p channels) ---------------------
    if (wq == 0) {
#pragma unroll
        for (int m = 0; m < 3; ++m) {
            int mt = wm + m * 8;
#pragma unroll
            for (int h = 0; h < 2; ++h) {
                int r = mt * 16 + g + 8 * h;
                float p0 = 0.f, p1 = 0.f;
#pragma unroll
                for (int nt = 0; nt < 4; ++nt) {
#pragma unroll
                    for (int j = 0; j < 2; ++j) {
                        int ch = nt * 8 + 2 * q + j;
                        float vv = fmaxf(acc[m][nt][2 * h + j] + smf[OFF_CP + ch], 0.f);
                        p0 += vv * smf[OFF_WO + ch];
                        p1 += vv * smf[OFF_WO + 32 + ch];
                    }
                }
                p0 += __shfl_xor_sync(0xffffffffu, p0, 1);
                p0 += __shfl_xor_sync(0xffffffffu, p0, 2);
                p1 += __shfl_xor_sync(0xffffffffu, p1, 1);
                p1 += __shfl_xor_sync(0xffffffffu, p1, 2);
                if (q == 0 && r < HW) {
                    out[img * OUTW + r]          = p0;
                    out[AUXOFF + img * OUTW + r] = p1;
                }
            }
        }
    }
}

extern "C" void kernel_launch(void* const* d_in, const int* in_sizes, int n_in,
                              void* d_out, int out_size) {
    (void)in_sizes; (void)n_in; (void)out_size;
    policy_init<<<64, 256>>>(
        (const float*)d_in[1], (const float*)d_in[2],
        (const float*)d_in[10], (const float*)d_in[5]);
    cudaFuncSetAttribute(policy_head_kernel,
                         cudaFuncAttributeMaxDynamicSharedMemorySize, SMEM_BYTES);
    policy_head_kernel<<<NIMG, 512, SMEM_BYTES>>>(
        (const float*)d_in[0],
        (const float*)d_in[3],  (const float*)d_in[4],  (const float*)d_in[5],
        (const float*)d_in[6],  (const float*)d_in[7],  (const float*)d_in[8],
        (const float*)d_in[9],  (const float*)d_in[10], (const float*)d_in[11],
        (const float*)d_in[12], (const float*)d_in[13],
        (float*)d_out);
}